// round 1
// baseline (speedup 1.0000x reference)
#include <cuda_runtime.h>
#include <cuda_bf16.h>
#include <math.h>

// ---------------- problem constants ----------------
#define IN_DIM   36
#define D_MODEL  32
#define D_INNER  64
#define D_STATE  8
#define NHEADS   8
#define HEADDIM  8
#define CONV_DIM 80            // D_INNER + 2*D_STATE
#define D_IN_PROJ 152          // 2*64 + 2*8 + 8
#define NORM_EPS 1e-5f

// staging layout (plain fp32, duplicated into f32x2 pairs at CTA fill)
//  [0,5472)      W1[j*36+k]   fused in_proj@f_out (152 x 36)
//  [5472,7520)   WoutT[d*32+o] = out_proj[o][d]*norm_w[d]  (64 x 32)
//  [7520,7672)   b1[152] = in_proj @ f_out_b
//  [7672,7752)   cs[80]  = conv_w[:,1]
//  [7752,7832)   cb[80]  = conv_b
//  [7832,7840)   dt_bias[8]
//  [7840,7848)   D_skip[8]
#define P_W1   0
#define P_WOUT 5472
#define P_B1   7520
#define P_CS   7672
#define P_CB   7752
#define P_DTB  7832
#define P_DSK  7840
#define P_TOTAL 7848

#define NTHREADS 128
#define SMEM_PAIRS (P_TOTAL + 8*NTHREADS)          // + per-thread coef scratch
#define SMEM_BYTES (SMEM_PAIRS * 8)

__device__ float g_params[P_TOTAL];

// ---------------- f32x2 helpers ----------------
typedef unsigned long long u64;

__device__ __forceinline__ u64 pk(float lo, float hi) {
    u64 r; asm("mov.b64 %0,{%1,%2};" : "=l"(r) : "f"(lo), "f"(hi)); return r;
}
__device__ __forceinline__ void upk(u64 p, float& lo, float& hi) {
    asm("mov.b64 {%0,%1},%2;" : "=f"(lo), "=f"(hi) : "l"(p));
}
__device__ __forceinline__ void fma2(u64& d, u64 a, u64 b) {
    asm("fma.rn.f32x2 %0,%1,%2,%0;" : "+l"(d) : "l"(a), "l"(b));
}
__device__ __forceinline__ u64 mul2(u64 a, u64 b) {
    u64 d; asm("mul.rn.f32x2 %0,%1,%2;" : "=l"(d) : "l"(a), "l"(b)); return d;
}
__device__ __forceinline__ u64 add2(u64 a, u64 b) {
    u64 d; asm("add.rn.f32x2 %0,%1,%2;" : "=l"(d) : "l"(a), "l"(b)); return d;
}

__device__ __forceinline__ float silu1(float v) {
    return v / (1.0f + __expf(-v));
}
__device__ __forceinline__ u64 silu2(u64 p) {
    float a, b; upk(p, a, b);
    return pk(silu1(a), silu1(b));
}
__device__ __forceinline__ float softplus1(float v) {
    return (v > 15.0f) ? v : log1pf(__expf(v));
}
__device__ __forceinline__ u64 softplus2(u64 p) {
    float a, b; upk(p, a, b);
    return pk(softplus1(a), softplus1(b));
}

// dot over K=36 of packed x with dup-pair weights, bias pre-loaded into acc
__device__ __forceinline__ u64 dot36(const u64* __restrict__ w,
                                     const u64* __restrict__ xv,
                                     u64 bias) {
    u64 a0 = bias, a1 = 0ull;
    const ulonglong2* w2 = (const ulonglong2*)w;
    #pragma unroll
    for (int k = 0; k < 18; k++) {
        ulonglong2 ww = w2[k];
        fma2(a0, xv[2*k],   ww.x);
        fma2(a1, xv[2*k+1], ww.y);
    }
    return add2(a0, a1);
}

// ---------------- prep: fold weights on device ----------------
__global__ void prep_kernel(const float* __restrict__ f_out_w,   // (32,36)
                            const float* __restrict__ f_out_b,   // (32,)
                            const float* __restrict__ in_proj_w, // (152,32)
                            const float* __restrict__ conv_w,    // (80,2)
                            const float* __restrict__ conv_b,    // (80,)
                            const float* __restrict__ dt_bias,   // (8,)
                            const float* __restrict__ D_skip,    // (8,)
                            const float* __restrict__ norm_w,    // (64,)
                            const float* __restrict__ out_proj_w)// (32,64)
{
    int t = blockIdx.x * blockDim.x + threadIdx.x;
    int stride = gridDim.x * blockDim.x;
    // fused W1[j][k] = sum_m in_proj[j][m] * f_out_w[m][k]
    for (int i = t; i < 152*36; i += stride) {
        int j = i / 36, k = i % 36;
        float s = 0.0f;
        #pragma unroll
        for (int m = 0; m < 32; m++) s += in_proj_w[j*32+m] * f_out_w[m*36+k];
        g_params[P_W1 + i] = s;
    }
    // WoutT[d][o] = out_proj[o][d] * norm_w[d]
    for (int i = t; i < 64*32; i += stride) {
        int d = i / 32, o = i % 32;
        g_params[P_WOUT + i] = out_proj_w[o*64+d] * norm_w[d];
    }
    // b1[j] = sum_m in_proj[j][m] * f_out_b[m]
    for (int i = t; i < 152; i += stride) {
        float s = 0.0f;
        #pragma unroll
        for (int m = 0; m < 32; m++) s += in_proj_w[i*32+m] * f_out_b[m];
        g_params[P_B1 + i] = s;
    }
    for (int i = t; i < 80; i += stride) {
        g_params[P_CS + i] = conv_w[i*2 + 1];
        g_params[P_CB + i] = conv_b[i];
    }
    for (int i = t; i < 8; i += stride) {
        g_params[P_DTB + i] = dt_bias[i];
        g_params[P_DSK + i] = D_skip[i];
    }
}

// ---------------- softmax over 32 logits -> 32 outputs ----------------
__device__ __forceinline__ void softmax_store(float* v, float sc,
                                              float* __restrict__ dst) {
    float m = -1e30f;
    #pragma unroll
    for (int o = 0; o < 32; o++) { v[o] *= sc; m = fmaxf(m, v[o]); }
    float s = 0.0f;
    #pragma unroll
    for (int o = 0; o < 32; o++) { v[o] = __expf(v[o] - m); s += v[o]; }
    float inv = 1.0f / s;
    float4* d4 = (float4*)dst;
    #pragma unroll
    for (int i = 0; i < 8; i++)
        d4[i] = make_float4(v[4*i]*inv, v[4*i+1]*inv, v[4*i+2]*inv, v[4*i+3]*inv);
}

// ---------------- main fused kernel (2 rows / thread, f32x2 packed) ----
__global__ __launch_bounds__(NTHREADS, 3)
void mamba_fused_kernel(const float* __restrict__ x,
                        float* __restrict__ out, int N)
{
    extern __shared__ u64 sm[];   // dup-pair weights + coef scratch

    // fill shared with duplicated pairs {w,w}
    for (int i = threadIdx.x; i < P_TOTAL; i += blockDim.x) {
        float w = g_params[i];
        sm[i] = pk(w, w);
    }
    __syncthreads();

    u64* scoef = sm + P_TOTAL;    // [8][NTHREADS], per-thread, conflict-free

    const int npairs = N >> 1;
    int gtid = blockIdx.x * blockDim.x + threadIdx.x;
    int gstride = gridDim.x * blockDim.x;

    for (int pair = gtid; pair < npairs; pair += gstride) {
        size_t r0 = (size_t)pair * 2;

        // ---- load 2 rows (36 floats each, 16B-aligned) and pack ----
        const float4* xp = (const float4*)(x + r0 * IN_DIM);
        u64 xv[36];
        #pragma unroll
        for (int i = 0; i < 9; i++) {
            float4 a = xp[i];
            float4 b = xp[i + 9];
            xv[4*i+0] = pk(a.x, b.x);
            xv[4*i+1] = pk(a.y, b.y);
            xv[4*i+2] = pk(a.z, b.z);
            xv[4*i+3] = pk(a.w, b.w);
        }

        // ---- phase A: B, C channels -> bc ; dt -> coef[h] ----
        u64 bc = 0ull;
        #pragma unroll 1
        for (int s = 0; s < 8; s++) {
            u64 Br = dot36(sm + P_W1 + (128+s)*36, xv, sm[P_B1 + 128 + s]);
            u64 Cr = dot36(sm + P_W1 + (136+s)*36, xv, sm[P_B1 + 136 + s]);
            u64 tb = sm[P_CB + 64 + s]; fma2(tb, Br, sm[P_CS + 64 + s]); tb = silu2(tb);
            u64 tc = sm[P_CB + 72 + s]; fma2(tc, Cr, sm[P_CS + 72 + s]); tc = silu2(tc);
            fma2(bc, tb, tc);
        }
        #pragma unroll 1
        for (int h = 0; h < 8; h++) {
            u64 dr = dot36(sm + P_W1 + (144+h)*36, xv, sm[P_B1 + 144 + h]);
            dr = add2(dr, sm[P_DTB + h]);
            dr = softplus2(dr);                        // dt
            u64 cf = sm[P_DSK + h];
            fma2(cf, dr, bc);                          // dt*bc + D_skip
            scoef[h * NTHREADS + threadIdx.x] = cf;
        }

        // ---- phase B: per-channel z/x, gate, accumulate GEMM2 + ss ----
        u64 L[32];
        #pragma unroll
        for (int o = 0; o < 32; o++) L[o] = 0ull;
        u64 ss = 0ull;

        #pragma unroll 1
        for (int d = 0; d < 64; d++) {
            u64 zr = dot36(sm + P_W1 + d*36,        xv, sm[P_B1 + d]);
            u64 xr = dot36(sm + P_W1 + (64+d)*36,   xv, sm[P_B1 + 64 + d]);
            u64 t  = sm[P_CB + d];
            fma2(t, xr, sm[P_CS + d]);                 // conv pointwise
            t = silu2(t);                              // xh
            u64 cf = scoef[(d >> 3) * NTHREADS + threadIdx.x];
            u64 y  = mul2(mul2(t, cf), silu2(zr));     // xh*(dt*bc+Dskip)*silu(z)
            fma2(ss, y, y);
            const ulonglong2* wrow = (const ulonglong2*)(sm + P_WOUT + d*32);
            #pragma unroll
            for (int o = 0; o < 32; o += 2) {
                ulonglong2 ww = wrow[o >> 1];
                fma2(L[o],   y, ww.x);
                fma2(L[o+1], y, ww.y);
            }
        }

        // ---- RMS scale + softmax per lane ----
        float ssl, ssh; upk(ss, ssl, ssh);
        float sc0 = rsqrtf(ssl * (1.0f/64.0f) + NORM_EPS);
        float sc1 = rsqrtf(ssh * (1.0f/64.0f) + NORM_EPS);

        float lo[32], hi[32];
        #pragma unroll
        for (int o = 0; o < 32; o++) upk(L[o], lo[o], hi[o]);

        softmax_store(lo, sc0, out + r0 * 32);
        softmax_store(hi, sc1, out + (r0 + 1) * 32);
    }
}

// ---------------- launch ----------------
extern "C" void kernel_launch(void* const* d_in, const int* in_sizes, int n_in,
                              void* d_out, int out_size)
{
    const float* x         = (const float*)d_in[0];
    const float* f_out_w   = (const float*)d_in[1];
    const float* f_out_b   = (const float*)d_in[2];
    const float* in_proj_w = (const float*)d_in[3];
    const float* conv_w    = (const float*)d_in[4];
    const float* conv_b    = (const float*)d_in[5];
    const float* dt_bias   = (const float*)d_in[6];
    // d_in[7] = A_log (unused by the reference math)
    const float* D_skip    = (const float*)d_in[8];
    const float* norm_w    = (const float*)d_in[9];
    const float* out_proj_w= (const float*)d_in[10];

    int N = in_sizes[0] / IN_DIM;

    prep_kernel<<<48, 128>>>(f_out_w, f_out_b, in_proj_w, conv_w, conv_b,
                             dt_bias, D_skip, norm_w, out_proj_w);

    cudaFuncSetAttribute(mamba_fused_kernel,
                         cudaFuncAttributeMaxDynamicSharedMemorySize,
                         SMEM_BYTES);
    mamba_fused_kernel<<<148 * 3, NTHREADS, SMEM_BYTES>>>(x, (float*)d_out, N);
}